// round 6
// baseline (speedup 1.0000x reference)
#include <cuda_runtime.h>
#include <cstdint>

#define N_NODES 50000
#define KNB     10
#define VROWS   200000
#define FDIM    128
#define HDIM    64
#define GDIM    256   // 4*H

typedef unsigned long long ull;

// scratch: projected forward table and backward gates (device globals — no allocs)
__device__ float g_P [(size_t)VROWS  * GDIM];   // 204.8 MB
__device__ float g_Gb[(size_t)N_NODES * GDIM];  //  51.2 MB

// ---------------- f32x2 helpers (Blackwell packed fp32) ----------------
static __device__ __forceinline__ ull ffma2(ull a, ull b, ull c) {
    ull d; asm("fma.rn.f32x2 %0, %1, %2, %3;" : "=l"(d) : "l"(a), "l"(b), "l"(c)); return d;
}
static __device__ __forceinline__ ull dup2(float x) {
    ull r; asm("mov.b64 %0, {%1, %1};" : "=l"(r) : "f"(x)); return r;
}
static __device__ __forceinline__ float2 upk(ull v) {
    float2 r; asm("mov.b64 {%0, %1}, %2;" : "=f"(r.x), "=f"(r.y) : "l"(v)); return r;
}
static __device__ __forceinline__ float sigm(float x) {
    return 1.0f / (1.0f + __expf(-x));
}

// ============================================================================
// Projection kernel: out[row, gbase+gg] = sum_f src[row][f] * W[gbase+gg][f] + b1[g]+b2[g]
// BM=32 rows x BN=128 gates per block (blockIdx.y selects gate half).
// GATHER=false: rows = embed table rows (forward table P).
// GATHER=true : rows = E[idx[n][K-1]] (backward gates Gb), store guarded by nrows.
// Inner loop: gate-pair-packed FFMA2; W transposed in smem (pad 132), x duplicated
// in smem as {x,x} u64 so every operand is a vector LDS with zero pack movs on x.
// ============================================================================
#define PBM 32
#define PBN 128
#define WS_STRIDE 132
#define PROJ_SMEM (FDIM * WS_STRIDE * 4 + PBM * FDIM * 8)  // 67584 + 32768 = 100352

template<bool GATHER>
__global__ __launch_bounds__(256) void proj_kernel(
    const float* __restrict__ E, const float* __restrict__ W,
    const float* __restrict__ b1, const float* __restrict__ b2,
    const int* __restrict__ nidx, int nrows)
{
    extern __shared__ char smem[];
    float* WsT = (float*)smem;                          // [128][132] transposed W
    ull*   Es2 = (ull*)(smem + FDIM * WS_STRIDE * 4);   // [32][128] duplicated x
    __shared__ int idxs[PBM];

    const int tid   = threadIdx.x;
    const int v0    = blockIdx.x * PBM;
    const int gbase = blockIdx.y * PBN;

    if (GATHER) {
        if (tid < PBM) {
            int n = v0 + tid; if (n >= nrows) n = nrows - 1;
            idxs[tid] = nidx[n * KNB + (KNB - 1)];
        }
        __syncthreads();
    }

    // load W chunk transposed: WsT[f][gg] = W[(gbase+gg)*F + f]
    for (int lin = tid; lin < PBN * FDIM; lin += 256) {
        int gg = lin >> 7, f = lin & 127;
        WsT[f * WS_STRIDE + gg] = W[(size_t)(gbase + gg) * FDIM + f];
    }
    // load 32 source rows, each element duplicated into a u64 pair
    for (int lin4 = tid; lin4 < PBM * FDIM / 4; lin4 += 256) {
        int r = lin4 >> 5;
        int f = (lin4 & 31) * 4;
        const float* src = GATHER ? (E + (size_t)idxs[r] * FDIM)
                                  : (E + (size_t)(v0 + r) * FDIM);
        float4 v = *(const float4*)(src + f);
        ull* dst = &Es2[r * FDIM + f];
        ulonglong2 a, b;
        a.x = dup2(v.x); a.y = dup2(v.y);
        b.x = dup2(v.z); b.y = dup2(v.w);
        *(ulonglong2*)(dst)     = a;
        *(ulonglong2*)(dst + 2) = b;
    }
    __syncthreads();

    const int tx = tid & 31, ty = tid >> 5;
    const int g0 = tx * 4;   // 4 gates per thread (2 packed pairs)
    const int r0 = ty * 4;   // 4 rows per thread

    ull acc[4][2];
    #pragma unroll
    for (int r = 0; r < 4; ++r) { acc[r][0] = 0ull; acc[r][1] = 0ull; }

    #pragma unroll
    for (int f = 0; f < FDIM; f += 2) {
        ulonglong2 wa = *(const ulonglong2*)&WsT[f * WS_STRIDE + g0];       // gates g0..g0+3 @ f
        ulonglong2 wb = *(const ulonglong2*)&WsT[(f + 1) * WS_STRIDE + g0]; // @ f+1
        #pragma unroll
        for (int r = 0; r < 4; ++r) {
            ulonglong2 x2 = *(const ulonglong2*)&Es2[(r0 + r) * FDIM + f];  // {dup(x_f), dup(x_f1)}
            acc[r][0] = ffma2(wa.x, x2.x, acc[r][0]);
            acc[r][1] = ffma2(wa.y, x2.x, acc[r][1]);
            acc[r][0] = ffma2(wb.x, x2.y, acc[r][0]);
            acc[r][1] = ffma2(wb.y, x2.y, acc[r][1]);
        }
    }

    float4 bb;
    {
        float4 t1 = *(const float4*)(b1 + gbase + g0);
        float4 t2 = *(const float4*)(b2 + gbase + g0);
        bb.x = t1.x + t2.x; bb.y = t1.y + t2.y; bb.z = t1.z + t2.z; bb.w = t1.w + t2.w;
    }
    float* outp = GATHER ? g_Gb : g_P;
    #pragma unroll
    for (int r = 0; r < 4; ++r) {
        int row = v0 + r0 + r;
        if (row < nrows) {
            float2 p0 = upk(acc[r][0]);
            float2 p1 = upk(acc[r][1]);
            float4 o = make_float4(p0.x + bb.x, p0.y + bb.y, p1.x + bb.z, p1.y + bb.w);
            *(float4*)&outp[(size_t)row * GDIM + gbase + g0] = o;
        }
    }
}

// ============================================================================
// Recurrence kernel: 16 nodes per block, 256 threads (thread = one gate dim).
// Per step: gather projected gates from g_P (coalesced 1KB/node), matvec
// gates += Whh_f @ h with node-pair-packed FFMA2, stage gates in smem, cell
// update (c kept in registers of fixed owner threads), h back to smem.
// After 10 steps: forward half of output. Then backward single-cell from g_Gb.
// ============================================================================
#define NB 16
#define WS2_STRIDE 65   // [256][65] pad: bank(65g+j)=(g+j)%32 -> conflict-free
#define HS_STRIDE  20   // [64][20]: rows 80B -> 16B-aligned u64x2 node-pair loads
#define GS_STRIDE  18   // [256][18]: 2-way max on stores/reads
#define LSTM_SMEM (GDIM*WS2_STRIDE*4 + HDIM*HS_STRIDE*4 + GDIM*GS_STRIDE*4 + NB*KNB*4) // 90752

__global__ __launch_bounds__(256) void lstm_kernel(
    const int* __restrict__ nidx, const float* __restrict__ Whh,
    float* __restrict__ out)
{
    extern __shared__ char smem[];
    float* Ws   = (float*)smem;                      // [256][65]
    float* hs   = Ws + GDIM * WS2_STRIDE;            // [64][20]  (node-inner)
    float* gs   = hs + HDIM * HS_STRIDE;             // [256][18] gate staging
    int*   idxs = (int*)(gs + GDIM * GS_STRIDE);     // [16*10]

    const int tid = threadIdx.x;
    const int n0  = blockIdx.x * NB;

    if (tid < NB * KNB) idxs[tid] = nidx[n0 * KNB + tid];
    for (int lin = tid; lin < GDIM * HDIM; lin += 256) {
        int gg = lin >> 6, jj = lin & 63;
        Ws[gg * WS2_STRIDE + jj] = Whh[lin];
    }
    __syncthreads();

    const int g    = tid;        // gate dim 0..255
    const int j    = tid & 63;   // cell-phase hidden dim
    const int msub = tid >> 6;   // cell-phase node group
    float c[4] = {0.f, 0.f, 0.f, 0.f};

    for (int k = 0; k < KNB; ++k) {
        // gather projected gates (issued before matvec -> full latency overlap)
        float gv[NB];
        #pragma unroll
        for (int m = 0; m < NB; ++m)
            gv[m] = g_P[(size_t)idxs[m * KNB + k] * GDIM + g];

        ull acc[NB / 2];
        #pragma unroll
        for (int mp = 0; mp < NB / 2; ++mp) acc[mp] = 0ull;

        if (k > 0) {
            const float* wrow = Ws + g * WS2_STRIDE;
            #pragma unroll
            for (int jj = 0; jj < HDIM; ++jj) {
                ull w2 = dup2(wrow[jj]);
                const ulonglong2* hrow = (const ulonglong2*)(hs + jj * HS_STRIDE);
                ulonglong2 h01 = hrow[0], h23 = hrow[1], h45 = hrow[2], h67 = hrow[3];
                acc[0] = ffma2(w2, h01.x, acc[0]);
                acc[1] = ffma2(w2, h01.y, acc[1]);
                acc[2] = ffma2(w2, h23.x, acc[2]);
                acc[3] = ffma2(w2, h23.y, acc[3]);
                acc[4] = ffma2(w2, h45.x, acc[4]);
                acc[5] = ffma2(w2, h45.y, acc[5]);
                acc[6] = ffma2(w2, h67.x, acc[6]);
                acc[7] = ffma2(w2, h67.y, acc[7]);
            }
        }
        #pragma unroll
        for (int mp = 0; mp < NB / 2; ++mp) {
            float2 v = upk(acc[mp]);
            *(float2*)&gs[g * GS_STRIDE + 2 * mp] =
                make_float2(v.x + gv[2 * mp], v.y + gv[2 * mp + 1]);
        }
        __syncthreads();

        // cell update: thread owns (msub*4+q, j) cells; c stays in registers
        #pragma unroll
        for (int q = 0; q < 4; ++q) {
            int m = msub * 4 + q;
            float gi = gs[(0 * HDIM + j) * GS_STRIDE + m];
            float gf = gs[(1 * HDIM + j) * GS_STRIDE + m];
            float gz = gs[(2 * HDIM + j) * GS_STRIDE + m];
            float go = gs[(3 * HDIM + j) * GS_STRIDE + m];
            float iv = sigm(gi), fv = sigm(gf), zv = tanhf(gz), ov = sigm(go);
            c[q] = fv * c[q] + iv * zv;
            float h = ov * tanhf(c[q]);
            hs[j * HS_STRIDE + m] = h;
            if (k == KNB - 1) out[(size_t)(n0 + m) * 128 + j] = h;
        }
        __syncthreads();
    }

    // backward direction: single cell from zero state (h@Whh term vanishes)
    {
        float gv[NB];
        #pragma unroll
        for (int m = 0; m < NB; ++m)
            gv[m] = g_Gb[(size_t)(n0 + m) * GDIM + g];
        #pragma unroll
        for (int mp = 0; mp < NB / 2; ++mp)
            *(float2*)&gs[g * GS_STRIDE + 2 * mp] = make_float2(gv[2 * mp], gv[2 * mp + 1]);
        __syncthreads();
        #pragma unroll
        for (int q = 0; q < 4; ++q) {
            int m = msub * 4 + q;
            float gi = gs[(0 * HDIM + j) * GS_STRIDE + m];
            float gz = gs[(2 * HDIM + j) * GS_STRIDE + m];
            float go = gs[(3 * HDIM + j) * GS_STRIDE + m];
            float cb = sigm(gi) * tanhf(gz);           // c = i*g   (f*c0 = 0)
            float hb = sigm(go) * tanhf(cb);
            out[(size_t)(n0 + m) * 128 + HDIM + j] = hb;
        }
    }
}

// ============================================================================
extern "C" void kernel_launch(void* const* d_in, const int* in_sizes, int n_in,
                              void* d_out, int out_size) {
    const int*   nidx  = (const int*)  d_in[0];
    const float* E     = (const float*)d_in[1];
    const float* Wih_f = (const float*)d_in[2];
    const float* Whh_f = (const float*)d_in[3];
    const float* bih_f = (const float*)d_in[4];
    const float* bhh_f = (const float*)d_in[5];
    const float* Wih_b = (const float*)d_in[6];
    const float* Whh_b = (const float*)d_in[7];  // unused: h0 = 0
    const float* bih_b = (const float*)d_in[8];
    const float* bhh_b = (const float*)d_in[9];
    float* out = (float*)d_out;
    (void)Whh_b; (void)in_sizes; (void)n_in; (void)out_size;

    cudaFuncSetAttribute(proj_kernel<false>, cudaFuncAttributeMaxDynamicSharedMemorySize, PROJ_SMEM);
    cudaFuncSetAttribute(proj_kernel<true>,  cudaFuncAttributeMaxDynamicSharedMemorySize, PROJ_SMEM);
    cudaFuncSetAttribute(lstm_kernel,        cudaFuncAttributeMaxDynamicSharedMemorySize, LSTM_SMEM);

    // 1) forward projected table: P = E @ Wih_f^T + (bih_f + bhh_f)
    proj_kernel<false><<<dim3(VROWS / PBM, 2), 256, PROJ_SMEM>>>(
        E, Wih_f, bih_f, bhh_f, nullptr, VROWS);
    // 2) backward gates: Gb[n] = Wih_b @ E[idx[n][K-1]] + (bih_b + bhh_b)
    proj_kernel<true><<<dim3((N_NODES + PBM - 1) / PBM, 2), 256, PROJ_SMEM>>>(
        E, Wih_b, bih_b, bhh_b, nidx, N_NODES);
    // 3) forward recurrence + both output halves
    lstm_kernel<<<N_NODES / NB, 256, LSTM_SMEM>>>(nidx, Whh_f, out);
}

// round 8
// speedup vs baseline: 1.4318x; 1.4318x over previous
#include <cuda_runtime.h>
#include <cuda_bf16.h>
#include <cstdint>

#define N_NODES 50000
#define KNB     10
#define VROWS   200000
#define FDIM    128
#define HDIM    64
#define GDIM    256   // 4*H

typedef unsigned long long ull;

// scratch: projected forward table and backward gates (device globals — no allocs)
__device__ float g_P [(size_t)VROWS  * GDIM];   // 204.8 MB
__device__ float g_Gb[(size_t)N_NODES * GDIM];  //  51.2 MB

// ---------------- generic helpers ----------------
static __device__ __forceinline__ ull ffma2(ull a, ull b, ull c) {
    ull d; asm("fma.rn.f32x2 %0, %1, %2, %3;" : "=l"(d) : "l"(a), "l"(b), "l"(c)); return d;
}
static __device__ __forceinline__ ull dup2(float x) {
    ull r; asm("mov.b64 %0, {%1, %1};" : "=l"(r) : "f"(x)); return r;
}
static __device__ __forceinline__ float2 upk(ull v) {
    float2 r; asm("mov.b64 {%0, %1}, %2;" : "=f"(r.x), "=f"(r.y) : "l"(v)); return r;
}
static __device__ __forceinline__ float sigm(float x) {
    return 1.0f / (1.0f + __expf(-x));
}
static __device__ __forceinline__ unsigned pack2bf(__nv_bfloat16 a, __nv_bfloat16 b) {
    __nv_bfloat162 t(a, b);
    return *(unsigned*)&t;
}
// warp-level bf16 HMMA (arch-portable; no sm_103a target feature needed)
static __device__ __forceinline__ void mma16816(float* c,
    uint32_t a0, uint32_t a1, uint32_t a2, uint32_t a3, uint32_t b0, uint32_t b1) {
    asm volatile(
        "mma.sync.aligned.m16n8k16.row.col.f32.bf16.bf16.f32 "
        "{%0,%1,%2,%3}, {%4,%5,%6,%7}, {%8,%9}, {%0,%1,%2,%3};"
        : "+f"(c[0]), "+f"(c[1]), "+f"(c[2]), "+f"(c[3])
        : "r"(a0), "r"(a1), "r"(a2), "r"(a3), "r"(b0), "r"(b1));
}

// ============================================================================
// HMMA projection: out[row, gbase+g] = sum_f src[row][f] * W[gbase+g][f] + b1+b2
// fp32 via 3-term bf16 split: Ah*Bh + Ah*Bl + Al*Bh (fp32 accumulators).
// CTA tile: 128 rows x 128 gates, K=128. 8 warps (4 m x 2 n), warp tile 32x64.
// smem rows padded to 68 u32 -> LDS bank = (4g + t) % 32: conflict-free for the
// 8x4 lane grid of every fragment load. k-contiguous storage matches the
// row.col fragment packing ({k,k+1} bf16 per u32) for both A and B.
// GATHER=false: rows = table rows (-> g_P). GATHER=true: rows = E[idx[n][K-1]] (-> g_Gb).
// ============================================================================
#define ROW_U32 68          // 64 data u32 (128 bf16) + 4 pad
#define TILE_BYTES (128 * ROW_U32 * 4)      // 34816
#define OFF_IDX  0          // 128 ints
#define OFF_BIAS 512        // 128 floats (this block's gate half)
#define OFF_AH   1024
#define OFF_AL   (OFF_AH + TILE_BYTES)      // 35840
#define OFF_BH   (OFF_AL + TILE_BYTES)      // 70656
#define OFF_BL   (OFF_BH + TILE_BYTES)      // 105472
#define TC_SMEM  (OFF_BL + TILE_BYTES)      // 140288

template<bool GATHER>
__global__ __launch_bounds__(256) void proj_tc(
    const float* __restrict__ E, const float* __restrict__ W,
    const float* __restrict__ b1, const float* __restrict__ b2,
    const int* __restrict__ nidx, int nrows)
{
    extern __shared__ __align__(16) char smem[];
    int*      idxs = (int*)(smem + OFF_IDX);
    float*    bias = (float*)(smem + OFF_BIAS);
    uint32_t* Ah   = (uint32_t*)(smem + OFF_AH);
    uint32_t* Al   = (uint32_t*)(smem + OFF_AL);
    uint32_t* Bh   = (uint32_t*)(smem + OFF_BH);
    uint32_t* Bl   = (uint32_t*)(smem + OFF_BL);

    const int tid   = threadIdx.x;
    const int r0    = blockIdx.x * 128;
    const int gbase = blockIdx.y * 128;

    if (tid < 128) {
        bias[tid] = b1[gbase + tid] + b2[gbase + tid];
        if (GATHER) {
            int n = r0 + tid; if (n >= nrows) n = nrows - 1;
            idxs[tid] = nidx[n * KNB + (KNB - 1)];
        }
    }
    if (GATHER) __syncthreads();

    // ---- fill B (weights, 128 gates x 128 k) hi/lo ----
    for (int u = tid; u < 128 * 16; u += 256) {
        int g = u >> 4, c8 = (u & 15) * 8;
        const float* src = W + (size_t)(gbase + g) * FDIM + c8;
        float4 v0 = *(const float4*)(src);
        float4 v1 = *(const float4*)(src + 4);
        float f[8] = {v0.x, v0.y, v0.z, v0.w, v1.x, v1.y, v1.z, v1.w};
        __nv_bfloat16 h[8], l[8];
        #pragma unroll
        for (int i = 0; i < 8; ++i) {
            h[i] = __float2bfloat16_rn(f[i]);
            l[i] = __float2bfloat16_rn(f[i] - __bfloat162float(h[i]));
        }
        int du = g * ROW_U32 + (c8 >> 1);
        *(uint4*)&Bh[du] = make_uint4(pack2bf(h[0],h[1]), pack2bf(h[2],h[3]), pack2bf(h[4],h[5]), pack2bf(h[6],h[7]));
        *(uint4*)&Bl[du] = make_uint4(pack2bf(l[0],l[1]), pack2bf(l[2],l[3]), pack2bf(l[4],l[5]), pack2bf(l[6],l[7]));
    }
    // ---- fill A (rows, 128 x 128 k) hi/lo ----
    for (int u = tid; u < 128 * 16; u += 256) {
        int r = u >> 4, c8 = (u & 15) * 8;
        size_t srow;
        if (GATHER) srow = (size_t)idxs[r];
        else { int rr = r0 + r; if (rr >= nrows) rr = nrows - 1; srow = (size_t)rr; }
        const float* src = E + srow * FDIM + c8;
        float4 v0 = *(const float4*)(src);
        float4 v1 = *(const float4*)(src + 4);
        float f[8] = {v0.x, v0.y, v0.z, v0.w, v1.x, v1.y, v1.z, v1.w};
        __nv_bfloat16 h[8], l[8];
        #pragma unroll
        for (int i = 0; i < 8; ++i) {
            h[i] = __float2bfloat16_rn(f[i]);
            l[i] = __float2bfloat16_rn(f[i] - __bfloat162float(h[i]));
        }
        int du = r * ROW_U32 + (c8 >> 1);
        *(uint4*)&Ah[du] = make_uint4(pack2bf(h[0],h[1]), pack2bf(h[2],h[3]), pack2bf(h[4],h[5]), pack2bf(h[6],h[7]));
        *(uint4*)&Al[du] = make_uint4(pack2bf(l[0],l[1]), pack2bf(l[2],l[3]), pack2bf(l[4],l[5]), pack2bf(l[6],l[7]));
    }
    __syncthreads();

    // ---- warp-tiled MMA: warp (wm, wn) owns rows wm*32..+31, gates wn*64..+63 ----
    const int wid  = tid >> 5, lane = tid & 31;
    const int wm   = wid & 3, wn = wid >> 2;
    const int g    = lane >> 2, t = lane & 3;

    float c[2][8][4];
    #pragma unroll
    for (int mi = 0; mi < 2; ++mi)
        #pragma unroll
        for (int ni = 0; ni < 8; ++ni)
            #pragma unroll
            for (int q = 0; q < 4; ++q) c[mi][ni][q] = 0.f;

    const uint32_t* Abase[3] = {Ah, Ah, Al};
    const uint32_t* Bbase[3] = {Bh, Bl, Bh};
    #pragma unroll
    for (int term = 0; term < 3; ++term) {
        const uint32_t* As = Abase[term];
        const uint32_t* Bs = Bbase[term];
        #pragma unroll
        for (int ks = 0; ks < 8; ++ks) {
            const int kc = ks * 8;      // u32 column base (16 bf16 per k-step)
            uint32_t a[2][4];
            #pragma unroll
            for (int mi = 0; mi < 2; ++mi) {
                const uint32_t* ar = As + (wm * 32 + mi * 16 + g) * ROW_U32;
                a[mi][0] = ar[kc + t];
                a[mi][1] = ar[8 * ROW_U32 + kc + t];
                a[mi][2] = ar[kc + 4 + t];
                a[mi][3] = ar[8 * ROW_U32 + kc + 4 + t];
            }
            #pragma unroll
            for (int ni = 0; ni < 8; ++ni) {
                const uint32_t* br = Bs + (wn * 64 + ni * 8 + g) * ROW_U32;
                uint32_t b0 = br[kc + t];
                uint32_t b1 = br[kc + 4 + t];
                mma16816(c[0][ni], a[0][0], a[0][1], a[0][2], a[0][3], b0, b1);
                mma16816(c[1][ni], a[1][0], a[1][1], a[1][2], a[1][3], b0, b1);
            }
        }
    }

    // ---- bias + store ----
    float* outp = GATHER ? g_Gb : g_P;
    #pragma unroll
    for (int mi = 0; mi < 2; ++mi) {
        int row0 = r0 + wm * 32 + mi * 16 + g;
        #pragma unroll
        for (int ni = 0; ni < 8; ++ni) {
            int lc  = wn * 64 + ni * 8 + 2 * t;      // local gate col
            float bx = bias[lc], by = bias[lc + 1];
            if (row0 < nrows)
                *(float2*)&outp[(size_t)row0 * GDIM + gbase + lc] =
                    make_float2(c[mi][ni][0] + bx, c[mi][ni][1] + by);
            if (row0 + 8 < nrows)
                *(float2*)&outp[(size_t)(row0 + 8) * GDIM + gbase + lc] =
                    make_float2(c[mi][ni][2] + bx, c[mi][ni][3] + by);
        }
    }
}

// ============================================================================
// Recurrence kernel (unchanged from R5): 16 nodes/block, 256 threads.
// ============================================================================
#define NB 16
#define WS2_STRIDE 65
#define HS_STRIDE  20
#define GS_STRIDE  18
#define LSTM_SMEM (GDIM*WS2_STRIDE*4 + HDIM*HS_STRIDE*4 + GDIM*GS_STRIDE*4 + NB*KNB*4) // 90752

__global__ __launch_bounds__(256) void lstm_kernel(
    const int* __restrict__ nidx, const float* __restrict__ Whh,
    float* __restrict__ out)
{
    extern __shared__ char smem[];
    float* Ws   = (float*)smem;                      // [256][65]
    float* hs   = Ws + GDIM * WS2_STRIDE;            // [64][20]
    float* gs   = hs + HDIM * HS_STRIDE;             // [256][18]
    int*   idxs = (int*)(gs + GDIM * GS_STRIDE);     // [16*10]

    const int tid = threadIdx.x;
    const int n0  = blockIdx.x * NB;

    if (tid < NB * KNB) idxs[tid] = nidx[n0 * KNB + tid];
    for (int lin = tid; lin < GDIM * HDIM; lin += 256) {
        int gg = lin >> 6, jj = lin & 63;
        Ws[gg * WS2_STRIDE + jj] = Whh[lin];
    }
    __syncthreads();

    const int g    = tid;
    const int j    = tid & 63;
    const int msub = tid >> 6;
    float c[4] = {0.f, 0.f, 0.f, 0.f};

    for (int k = 0; k < KNB; ++k) {
        float gv[NB];
        #pragma unroll
        for (int m = 0; m < NB; ++m)
            gv[m] = g_P[(size_t)idxs[m * KNB + k] * GDIM + g];

        ull acc[NB / 2];
        #pragma unroll
        for (int mp = 0; mp < NB / 2; ++mp) acc[mp] = 0ull;

        if (k > 0) {
            const float* wrow = Ws + g * WS2_STRIDE;
            #pragma unroll
            for (int jj = 0; jj < HDIM; ++jj) {
                ull w2 = dup2(wrow[jj]);
                const ulonglong2* hrow = (const ulonglong2*)(hs + jj * HS_STRIDE);
                ulonglong2 h01 = hrow[0], h23 = hrow[1], h45 = hrow[2], h67 = hrow[3];
                acc[0] = ffma2(w2, h01.x, acc[0]);
                acc[1] = ffma2(w2, h01.y, acc[1]);
                acc[2] = ffma2(w2, h23.x, acc[2]);
                acc[3] = ffma2(w2, h23.y, acc[3]);
                acc[4] = ffma2(w2, h45.x, acc[4]);
                acc[5] = ffma2(w2, h45.y, acc[5]);
                acc[6] = ffma2(w2, h67.x, acc[6]);
                acc[7] = ffma2(w2, h67.y, acc[7]);
            }
        }
        #pragma unroll
        for (int mp = 0; mp < NB / 2; ++mp) {
            float2 v = upk(acc[mp]);
            *(float2*)&gs[g * GS_STRIDE + 2 * mp] =
                make_float2(v.x + gv[2 * mp], v.y + gv[2 * mp + 1]);
        }
        __syncthreads();

        #pragma unroll
        for (int q = 0; q < 4; ++q) {
            int m = msub * 4 + q;
            float gi = gs[(0 * HDIM + j) * GS_STRIDE + m];
            float gf = gs[(1 * HDIM + j) * GS_STRIDE + m];
            float gz = gs[(2 * HDIM + j) * GS_STRIDE + m];
            float go = gs[(3 * HDIM + j) * GS_STRIDE + m];
            float iv = sigm(gi), fv = sigm(gf), zv = tanhf(gz), ov = sigm(go);
            c[q] = fv * c[q] + iv * zv;
            float h = ov * tanhf(c[q]);
            hs[j * HS_STRIDE + m] = h;
            if (k == KNB - 1) out[(size_t)(n0 + m) * 128 + j] = h;
        }
        __syncthreads();
    }

    // backward direction: single cell from zero state
    {
        float gv[NB];
        #pragma unroll
        for (int m = 0; m < NB; ++m)
            gv[m] = g_Gb[(size_t)(n0 + m) * GDIM + g];
        #pragma unroll
        for (int mp = 0; mp < NB / 2; ++mp)
            *(float2*)&gs[g * GS_STRIDE + 2 * mp] = make_float2(gv[2 * mp], gv[2 * mp + 1]);
        __syncthreads();
        #pragma unroll
        for (int q = 0; q < 4; ++q) {
            int m = msub * 4 + q;
            float gi = gs[(0 * HDIM + j) * GS_STRIDE + m];
            float gz = gs[(2 * HDIM + j) * GS_STRIDE + m];
            float go = gs[(3 * HDIM + j) * GS_STRIDE + m];
            float cb = sigm(gi) * tanhf(gz);
            float hb = sigm(go) * tanhf(cb);
            out[(size_t)(n0 + m) * 128 + HDIM + j] = hb;
        }
    }
}

// ============================================================================
extern "C" void kernel_launch(void* const* d_in, const int* in_sizes, int n_in,
                              void* d_out, int out_size) {
    const int*   nidx  = (const int*)  d_in[0];
    const float* E     = (const float*)d_in[1];
    const float* Wih_f = (const float*)d_in[2];
    const float* Whh_f = (const float*)d_in[3];
    const float* bih_f = (const float*)d_in[4];
    const float* bhh_f = (const float*)d_in[5];
    const float* Wih_b = (const float*)d_in[6];
    const float* Whh_b = (const float*)d_in[7];  // unused: h0 = 0
    const float* bih_b = (const float*)d_in[8];
    const float* bhh_b = (const float*)d_in[9];
    float* out = (float*)d_out;
    (void)Whh_b; (void)in_sizes; (void)n_in; (void)out_size;

    cudaFuncSetAttribute(proj_tc<false>, cudaFuncAttributeMaxDynamicSharedMemorySize, TC_SMEM);
    cudaFuncSetAttribute(proj_tc<true>,  cudaFuncAttributeMaxDynamicSharedMemorySize, TC_SMEM);
    cudaFuncSetAttribute(lstm_kernel,    cudaFuncAttributeMaxDynamicSharedMemorySize, LSTM_SMEM);

    // 1) forward projected table: P = E @ Wih_f^T + (bih_f + bhh_f)   [HMMA bf16 x3]
    proj_tc<false><<<dim3((VROWS + 127) / 128, 2), 256, TC_SMEM>>>(
        E, Wih_f, bih_f, bhh_f, nullptr, VROWS);
    // 2) backward gates: Gb[n] = Wih_b @ E[idx[n][K-1]] + (bih_b + bhh_b)
    proj_tc<true><<<dim3((N_NODES + 127) / 128, 2), 256, TC_SMEM>>>(
        E, Wih_b, bih_b, bhh_b, nidx, N_NODES);
    // 3) forward recurrence + both output halves
    lstm_kernel<<<N_NODES / NB, 256, LSTM_SMEM>>>(nidx, Whh_f, out);
}

// round 10
// speedup vs baseline: 1.8617x; 1.3002x over previous
#include <cuda_runtime.h>
#include <cuda_bf16.h>
#include <cstdint>

#define N_NODES 50000
#define KNB     10
#define VROWS   200000
#define FDIM    128
#define HDIM    64
#define GDIM    256   // 4*H

typedef unsigned long long ull;

// scratch: projected forward table and backward gates (device globals — no allocs)
__device__ float g_P [(size_t)VROWS  * GDIM];   // 204.8 MB
__device__ float g_Gb[(size_t)N_NODES * GDIM];  //  51.2 MB

// ---------------- helpers ----------------
static __device__ __forceinline__ float sigm(float x) {
    return 1.0f / (1.0f + __expf(-x));
}
static __device__ __forceinline__ unsigned pack2bf(__nv_bfloat16 a, __nv_bfloat16 b) {
    __nv_bfloat162 t(a, b);
    return *(unsigned*)&t;
}
// warp-level bf16 HMMA (arch-portable; compiles under compute_103 virtual)
static __device__ __forceinline__ void mma16816(float* c,
    uint32_t a0, uint32_t a1, uint32_t a2, uint32_t a3, uint32_t b0, uint32_t b1) {
    asm volatile(
        "mma.sync.aligned.m16n8k16.row.col.f32.bf16.bf16.f32 "
        "{%0,%1,%2,%3}, {%4,%5,%6,%7}, {%8,%9}, {%0,%1,%2,%3};"
        : "+f"(c[0]), "+f"(c[1]), "+f"(c[2]), "+f"(c[3])
        : "r"(a0), "r"(a1), "r"(a2), "r"(a3), "r"(b0), "r"(b1));
}
static __device__ __forceinline__ void split_bf(float f, __nv_bfloat16& h, __nv_bfloat16& l) {
    h = __float2bfloat16_rn(f);
    l = __float2bfloat16_rn(f - __bfloat162float(h));
}

// ============================================================================
// HMMA projection: out[row, gbase+g] = sum_f src[row][f] * W[gbase+g][f] + b1+b2
// fp32 via 3-term bf16 split: Ah*Bh + Ah*Bl + Al*Bh (fp32 accumulators).
// CTA tile: 128 rows x 64 gates, K=128 (smem 105 KB -> 2 CTAs/SM).
// 8 warps (4 m x 2 n), warp tile 32 rows x 32 gates.
// GATHER=false: rows = table rows (-> g_P). GATHER=true: rows = E[idx[n][K-1]] (-> g_Gb).
// ============================================================================
#define ROW_U32 68          // 64 data u32 (128 bf16) + 4 pad -> conflict-free frag LDS
#define TILE_A (128 * ROW_U32 * 4)          // 34816
#define TILE_B (64  * ROW_U32 * 4)          // 17408
#define OFF_IDX  0          // 128 ints
#define OFF_BIAS 512        // 64 floats
#define OFF_AH   1024
#define OFF_AL   (OFF_AH + TILE_A)          // 35840
#define OFF_BH   (OFF_AL + TILE_A)          // 70656
#define OFF_BL   (OFF_BH + TILE_B)          // 88064
#define TC_SMEM  (OFF_BL + TILE_B)          // 105472

template<bool GATHER>
__global__ __launch_bounds__(256, 2) void proj_tc(
    const float* __restrict__ E, const float* __restrict__ W,
    const float* __restrict__ b1, const float* __restrict__ b2,
    const int* __restrict__ nidx, int nrows)
{
    extern __shared__ __align__(16) char smem[];
    int*      idxs = (int*)(smem + OFF_IDX);
    float*    bias = (float*)(smem + OFF_BIAS);
    uint32_t* Ah   = (uint32_t*)(smem + OFF_AH);
    uint32_t* Al   = (uint32_t*)(smem + OFF_AL);
    uint32_t* Bh   = (uint32_t*)(smem + OFF_BH);
    uint32_t* Bl   = (uint32_t*)(smem + OFF_BL);

    const int tid   = threadIdx.x;
    const int r0    = blockIdx.x * 128;
    const int gbase = blockIdx.y * 64;

    if (tid < 64) bias[tid] = b1[gbase + tid] + b2[gbase + tid];
    if (GATHER && tid < 128) {
        int n = r0 + tid; if (n >= nrows) n = nrows - 1;
        idxs[tid] = nidx[n * KNB + (KNB - 1)];
    }
    if (GATHER) __syncthreads();

    // ---- fill B (weights, 64 gates x 128 k) hi/lo ----
    for (int u = tid; u < 64 * 16; u += 256) {
        int g = u >> 4, c8 = (u & 15) * 8;
        const float* src = W + (size_t)(gbase + g) * FDIM + c8;
        float4 v0 = *(const float4*)(src);
        float4 v1 = *(const float4*)(src + 4);
        float f[8] = {v0.x, v0.y, v0.z, v0.w, v1.x, v1.y, v1.z, v1.w};
        __nv_bfloat16 h[8], l[8];
        #pragma unroll
        for (int i = 0; i < 8; ++i) split_bf(f[i], h[i], l[i]);
        int du = g * ROW_U32 + (c8 >> 1);
        *(uint4*)&Bh[du] = make_uint4(pack2bf(h[0],h[1]), pack2bf(h[2],h[3]), pack2bf(h[4],h[5]), pack2bf(h[6],h[7]));
        *(uint4*)&Bl[du] = make_uint4(pack2bf(l[0],l[1]), pack2bf(l[2],l[3]), pack2bf(l[4],l[5]), pack2bf(l[6],l[7]));
    }
    // ---- fill A (rows, 128 x 128 k) hi/lo ----
    for (int u = tid; u < 128 * 16; u += 256) {
        int r = u >> 4, c8 = (u & 15) * 8;
        size_t srow;
        if (GATHER) srow = (size_t)idxs[r];
        else { int rr = r0 + r; if (rr >= nrows) rr = nrows - 1; srow = (size_t)rr; }
        const float* src = E + srow * FDIM + c8;
        float4 v0 = *(const float4*)(src);
        float4 v1 = *(const float4*)(src + 4);
        float f[8] = {v0.x, v0.y, v0.z, v0.w, v1.x, v1.y, v1.z, v1.w};
        __nv_bfloat16 h[8], l[8];
        #pragma unroll
        for (int i = 0; i < 8; ++i) split_bf(f[i], h[i], l[i]);
        int du = r * ROW_U32 + (c8 >> 1);
        *(uint4*)&Ah[du] = make_uint4(pack2bf(h[0],h[1]), pack2bf(h[2],h[3]), pack2bf(h[4],h[5]), pack2bf(h[6],h[7]));
        *(uint4*)&Al[du] = make_uint4(pack2bf(l[0],l[1]), pack2bf(l[2],l[3]), pack2bf(l[4],l[5]), pack2bf(l[6],l[7]));
    }
    __syncthreads();

    // ---- warp-tiled MMA: warp (wm, wn) owns rows wm*32..+31, gates wn*32..+31 ----
    const int wid  = tid >> 5, lane = tid & 31;
    const int wm   = wid & 3, wn = wid >> 2;
    const int g    = lane >> 2, t = lane & 3;

    float c[2][4][4];
    #pragma unroll
    for (int mi = 0; mi < 2; ++mi)
        #pragma unroll
        for (int ni = 0; ni < 4; ++ni)
            #pragma unroll
            for (int q = 0; q < 4; ++q) c[mi][ni][q] = 0.f;

    const uint32_t* Abase[3] = {Ah, Ah, Al};
    const uint32_t* Bbase[3] = {Bh, Bl, Bh};
    #pragma unroll
    for (int term = 0; term < 3; ++term) {
        const uint32_t* As = Abase[term];
        const uint32_t* Bs = Bbase[term];
        #pragma unroll
        for (int ks = 0; ks < 8; ++ks) {
            const int kc = ks * 8;
            uint32_t a[2][4];
            #pragma unroll
            for (int mi = 0; mi < 2; ++mi) {
                const uint32_t* ar = As + (wm * 32 + mi * 16 + g) * ROW_U32;
                a[mi][0] = ar[kc + t];
                a[mi][1] = ar[8 * ROW_U32 + kc + t];
                a[mi][2] = ar[kc + 4 + t];
                a[mi][3] = ar[8 * ROW_U32 + kc + 4 + t];
            }
            #pragma unroll
            for (int ni = 0; ni < 4; ++ni) {
                const uint32_t* br = Bs + (wn * 32 + ni * 8 + g) * ROW_U32;
                uint32_t b0 = br[kc + t];
                uint32_t b1 = br[kc + 4 + t];
                mma16816(c[0][ni], a[0][0], a[0][1], a[0][2], a[0][3], b0, b1);
                mma16816(c[1][ni], a[1][0], a[1][1], a[1][2], a[1][3], b0, b1);
            }
        }
    }

    // ---- bias + store ----
    float* outp = GATHER ? g_Gb : g_P;
    #pragma unroll
    for (int mi = 0; mi < 2; ++mi) {
        int row0 = r0 + wm * 32 + mi * 16 + g;
        #pragma unroll
        for (int ni = 0; ni < 4; ++ni) {
            int lc  = wn * 32 + ni * 8 + 2 * t;
            float bx = bias[lc], by = bias[lc + 1];
            if (row0 < nrows)
                *(float2*)&outp[(size_t)row0 * GDIM + gbase + lc] =
                    make_float2(c[mi][ni][0] + bx, c[mi][ni][1] + by);
            if (row0 + 8 < nrows)
                *(float2*)&outp[(size_t)(row0 + 8) * GDIM + gbase + lc] =
                    make_float2(c[mi][ni][2] + bx, c[mi][ni][3] + by);
        }
    }
}

// ============================================================================
// HMMA recurrence kernel: 32 nodes/block, 256 threads (8 warps).
// Per step k: R = H@Whh^T via 3-term bf16-split HMMA (32x256x64) staged to gs;
// cell phase: gates = g_P gather + R, cell update (c in regs), h split to
// bf16 hi/lo in smem for next step. Whh split hi/lo once per block.
// smem 112.9 KB -> 2 CTAs/SM.
// ============================================================================
#define LNB 32
#define BST 34                  // u32 row stride for Bh2/Bl2/Hh/Hl (2-way worst)
#define GST 260                 // f32 row stride for gs
// u32-offsets within dynamic smem
#define L_BH 0                              // 256*34 = 8704 u32
#define L_BL (L_BH + 256 * BST)             // 8704
#define L_HH (L_BL + 256 * BST)             // 17408
#define L_HL (L_HH + LNB * BST)             // 18496
#define L_GS (L_HL + LNB * BST)             // 19584
#define L_IX (L_GS + LNB * GST)             // 27904
#define LSTM_SMEM ((L_IX + LNB * KNB) * 4)  // 112896 bytes

__global__ __launch_bounds__(256, 2) void lstm_kernel(
    const int* __restrict__ nidx, const float* __restrict__ Whh,
    float* __restrict__ out)
{
    extern __shared__ __align__(16) char smraw[];
    uint32_t* sm   = (uint32_t*)smraw;
    uint32_t* Bh2  = sm + L_BH;
    uint32_t* Bl2  = sm + L_BL;
    uint32_t* Hh   = sm + L_HH;
    uint32_t* Hl   = sm + L_HL;
    float*    gs   = (float*)(sm + L_GS);
    int*      idxs = (int*)(sm + L_IX);

    const int tid  = threadIdx.x;
    const int wid  = tid >> 5, lane = tid & 31;
    const int n0   = blockIdx.x * LNB;

    // ---- prologue: indices (FIX: grid-stride loop, 320 entries > 256 threads) ----
    for (int u = tid; u < LNB * KNB; u += 256) {
        int m = u / KNB, kk = u % KNB;
        int n = n0 + m; if (n >= N_NODES) n = N_NODES - 1;
        idxs[m * KNB + kk] = nidx[n * KNB + kk];
    }
    // ---- Whh hi/lo split into smem (thread = gate row) ----
    {
        const float* wr = Whh + tid * HDIM;
        uint32_t* bh = Bh2 + tid * BST;
        uint32_t* bl = Bl2 + tid * BST;
        #pragma unroll
        for (int i = 0; i < 16; ++i) {
            float4 v = *(const float4*)(wr + i * 4);
            __nv_bfloat16 h0,l0,h1,l1,h2,l2,h3,l3;
            split_bf(v.x,h0,l0); split_bf(v.y,h1,l1);
            split_bf(v.z,h2,l2); split_bf(v.w,h3,l3);
            *(uint2*)&bh[i*2] = make_uint2(pack2bf(h0,h1), pack2bf(h2,h3));
            *(uint2*)&bl[i*2] = make_uint2(pack2bf(l0,l1), pack2bf(l2,l3));
        }
    }
    __syncthreads();

    // cell-phase identity
    const int j    = tid & 63;
    const int msub = tid >> 6;
    float cst[8];
    #pragma unroll
    for (int q = 0; q < 8; ++q) cst[q] = 0.f;

    for (int k = 0; k < KNB; ++k) {
        // ---- MMA phase: R = H @ Whh^T (3-term split), skip at k=0 ----
        if (k > 0) {
            const int wm = wid >> 2, wn = wid & 3;   // wm 0..1 (16 rows), wn 0..3 (64 gates)
            const int g = lane >> 2, t = lane & 3;

            uint32_t ah[4][4], al[4][4];
            const uint32_t* arh = Hh + (wm * 16 + g) * BST;
            const uint32_t* arl = Hl + (wm * 16 + g) * BST;
            #pragma unroll
            for (int ks = 0; ks < 4; ++ks) {
                const int kc = ks * 8;
                ah[ks][0] = arh[kc + t];           ah[ks][1] = arh[8 * BST + kc + t];
                ah[ks][2] = arh[kc + 4 + t];       ah[ks][3] = arh[8 * BST + kc + 4 + t];
                al[ks][0] = arl[kc + t];           al[ks][1] = arl[8 * BST + kc + t];
                al[ks][2] = arl[kc + 4 + t];       al[ks][3] = arl[8 * BST + kc + 4 + t];
            }
            float acc[8][4];
            #pragma unroll
            for (int ni = 0; ni < 8; ++ni)
                #pragma unroll
                for (int q = 0; q < 4; ++q) acc[ni][q] = 0.f;

            #pragma unroll
            for (int ni = 0; ni < 8; ++ni) {
                const uint32_t* brh = Bh2 + (wn * 64 + ni * 8 + g) * BST;
                const uint32_t* brl = Bl2 + (wn * 64 + ni * 8 + g) * BST;
                #pragma unroll
                for (int ks = 0; ks < 4; ++ks) {
                    const int kc = ks * 8;
                    uint32_t bh0 = brh[kc + t], bh1 = brh[kc + 4 + t];
                    uint32_t bl0 = brl[kc + t], bl1 = brl[kc + 4 + t];
                    mma16816(acc[ni], ah[ks][0], ah[ks][1], ah[ks][2], ah[ks][3], bh0, bh1);
                    mma16816(acc[ni], ah[ks][0], ah[ks][1], ah[ks][2], ah[ks][3], bl0, bl1);
                    mma16816(acc[ni], al[ks][0], al[ks][1], al[ks][2], al[ks][3], bh0, bh1);
                }
            }
            // stage R to gs
            const int r0 = wm * 16 + g;
            #pragma unroll
            for (int ni = 0; ni < 8; ++ni) {
                int col = wn * 64 + ni * 8 + 2 * t;
                *(float2*)&gs[r0 * GST + col]       = make_float2(acc[ni][0], acc[ni][1]);
                *(float2*)&gs[(r0 + 8) * GST + col] = make_float2(acc[ni][2], acc[ni][3]);
            }
        }
        __syncthreads();

        // ---- cell phase: thread (j, msub) owns nodes m = msub*8+q ----
        float xg[8][4];
        #pragma unroll
        for (int q = 0; q < 8; ++q) {
            int m = msub * 8 + q;
            const float* xp = g_P + (size_t)idxs[m * KNB + k] * GDIM + j;
            xg[q][0] = xp[0]; xg[q][1] = xp[64]; xg[q][2] = xp[128]; xg[q][3] = xp[192];
        }
        #pragma unroll
        for (int q = 0; q < 8; ++q) {
            int m = msub * 8 + q;
            float gi = xg[q][0], gf = xg[q][1], gz = xg[q][2], go = xg[q][3];
            if (k > 0) {
                const float* gr = gs + m * GST + j;
                gi += gr[0]; gf += gr[64]; gz += gr[128]; go += gr[192];
            }
            float iv = sigm(gi), fv = sigm(gf), zv = tanhf(gz), ov = sigm(go);
            cst[q] = fv * cst[q] + iv * zv;
            float h = ov * tanhf(cst[q]);
            // split h for next step's MMA
            __nv_bfloat16 hh, hl;
            split_bf(h, hh, hl);
            *(__nv_bfloat16*)((char*)(Hh + m * BST) + j * 2) = hh;
            *(__nv_bfloat16*)((char*)(Hl + m * BST) + j * 2) = hl;
            if (k == KNB - 1 && n0 + m < N_NODES)
                out[(size_t)(n0 + m) * 128 + j] = h;
        }
        __syncthreads();
    }

    // ---- backward direction: single cell from zero state ----
    #pragma unroll
    for (int q = 0; q < 8; ++q) {
        int m = msub * 8 + q, n = n0 + m;
        if (n < N_NODES) {
            const float* gb = g_Gb + (size_t)n * GDIM + j;
            float cb = sigm(gb[0]) * tanhf(gb[128]);
            float hb = sigm(gb[192]) * tanhf(cb);
            out[(size_t)n * 128 + HDIM + j] = hb;
        }
    }
}

// ============================================================================
extern "C" void kernel_launch(void* const* d_in, const int* in_sizes, int n_in,
                              void* d_out, int out_size) {
    const int*   nidx  = (const int*)  d_in[0];
    const float* E     = (const float*)d_in[1];
    const float* Wih_f = (const float*)d_in[2];
    const float* Whh_f = (const float*)d_in[3];
    const float* bih_f = (const float*)d_in[4];
    const float* bhh_f = (const float*)d_in[5];
    const float* Wih_b = (const float*)d_in[6];
    const float* Whh_b = (const float*)d_in[7];  // unused: h0 = 0
    const float* bih_b = (const float*)d_in[8];
    const float* bhh_b = (const float*)d_in[9];
    float* out = (float*)d_out;
    (void)Whh_b; (void)in_sizes; (void)n_in; (void)out_size;

    cudaFuncSetAttribute(proj_tc<false>, cudaFuncAttributeMaxDynamicSharedMemorySize, TC_SMEM);
    cudaFuncSetAttribute(proj_tc<true>,  cudaFuncAttributeMaxDynamicSharedMemorySize, TC_SMEM);
    cudaFuncSetAttribute(lstm_kernel,    cudaFuncAttributeMaxDynamicSharedMemorySize, LSTM_SMEM);

    // 1) forward projected table: P = E @ Wih_f^T + (bih_f + bhh_f)   [HMMA bf16 x3]
    proj_tc<false><<<dim3((VROWS + 127) / 128, 4), 256, TC_SMEM>>>(
        E, Wih_f, bih_f, bhh_f, nullptr, VROWS);
    // 2) backward gates: Gb[n] = Wih_b @ E[idx[n][K-1]] + (bih_b + bhh_b)
    proj_tc<true><<<dim3((N_NODES + 127) / 128, 4), 256, TC_SMEM>>>(
        E, Wih_b, bih_b, bhh_b, nidx, N_NODES);
    // 3) forward recurrence (HMMA) + both output halves
    lstm_kernel<<<(N_NODES + LNB - 1) / LNB, 256, LSTM_SMEM>>>(nidx, Whh_f, out);
}

// round 11
// speedup vs baseline: 1.8841x; 1.0121x over previous
#include <cuda_runtime.h>
#include <cuda_bf16.h>
#include <cstdint>

#define N_NODES 50000
#define KNB     10
#define VROWS   200000
#define FDIM    128
#define HDIM    64
#define GDIM    256   // 4*H

typedef unsigned long long ull;

// scratch: projected forward table and backward gates (device globals — no allocs)
__device__ float g_P [(size_t)VROWS  * GDIM];   // 204.8 MB
__device__ float g_Gb[(size_t)N_NODES * GDIM];  //  51.2 MB

// ---------------- helpers ----------------
static __device__ __forceinline__ float sigm(float x) {
    return 1.0f / (1.0f + __expf(-x));
}
static __device__ __forceinline__ unsigned pack2bf(__nv_bfloat16 a, __nv_bfloat16 b) {
    __nv_bfloat162 t(a, b);
    return *(unsigned*)&t;
}
// warp-level bf16 HMMA (arch-portable; compiles under compute_103 virtual)
static __device__ __forceinline__ void mma16816(float* c,
    uint32_t a0, uint32_t a1, uint32_t a2, uint32_t a3, uint32_t b0, uint32_t b1) {
    asm volatile(
        "mma.sync.aligned.m16n8k16.row.col.f32.bf16.bf16.f32 "
        "{%0,%1,%2,%3}, {%4,%5,%6,%7}, {%8,%9}, {%0,%1,%2,%3};"
        : "+f"(c[0]), "+f"(c[1]), "+f"(c[2]), "+f"(c[3])
        : "r"(a0), "r"(a1), "r"(a2), "r"(a3), "r"(b0), "r"(b1));
}
static __device__ __forceinline__ void split_bf(float f, __nv_bfloat16& h, __nv_bfloat16& l) {
    h = __float2bfloat16_rn(f);
    l = __float2bfloat16_rn(f - __bfloat162float(h));
}

// ============================================================================
// HMMA projection: out[row, gbase+g] = sum_f src[row][f] * W[gbase+g][f] + b1+b2
// fp32 via 3-term bf16 split: Ah*Bh + Ah*Bl + Al*Bh (fp32 accumulators).
// CTA tile: 128 rows x 64 gates, K=128 (smem 105 KB -> 2 CTAs/SM).
// GRID: x = gate quarter (4), y = row block -> the 4 co-resident blocks that
// share one A row-tile run concurrently and hit L2 (A DRAM traffic /4).
// GATHER=false: rows = table rows (-> g_P). GATHER=true: rows = E[idx[n][K-1]] (-> g_Gb).
// ============================================================================
#define ROW_U32 68          // 64 data u32 (128 bf16) + 4 pad -> conflict-free frag LDS
#define TILE_A (128 * ROW_U32 * 4)          // 34816
#define TILE_B (64  * ROW_U32 * 4)          // 17408
#define OFF_IDX  0          // 128 ints
#define OFF_BIAS 512        // 64 floats
#define OFF_AH   1024
#define OFF_AL   (OFF_AH + TILE_A)          // 35840
#define OFF_BH   (OFF_AL + TILE_A)          // 70656
#define OFF_BL   (OFF_BH + TILE_B)          // 88064
#define TC_SMEM  (OFF_BL + TILE_B)          // 105472

template<bool GATHER>
__global__ __launch_bounds__(256, 2) void proj_tc(
    const float* __restrict__ E, const float* __restrict__ W,
    const float* __restrict__ b1, const float* __restrict__ b2,
    const int* __restrict__ nidx, int nrows)
{
    extern __shared__ __align__(16) char smem[];
    int*      idxs = (int*)(smem + OFF_IDX);
    float*    bias = (float*)(smem + OFF_BIAS);
    uint32_t* Ah   = (uint32_t*)(smem + OFF_AH);
    uint32_t* Al   = (uint32_t*)(smem + OFF_AL);
    uint32_t* Bh   = (uint32_t*)(smem + OFF_BH);
    uint32_t* Bl   = (uint32_t*)(smem + OFF_BL);

    const int tid   = threadIdx.x;
    const int r0    = blockIdx.y * 128;       // row block (slow axis)
    const int gbase = blockIdx.x * 64;        // gate quarter (fast axis -> L2 reuse of A)

    if (tid < 64) bias[tid] = b1[gbase + tid] + b2[gbase + tid];
    if (GATHER && tid < 128) {
        int n = r0 + tid; if (n >= nrows) n = nrows - 1;
        idxs[tid] = nidx[n * KNB + (KNB - 1)];
    }
    if (GATHER) __syncthreads();

    // ---- fill B (weights, 64 gates x 128 k) hi/lo ----
    for (int u = tid; u < 64 * 16; u += 256) {
        int g = u >> 4, c8 = (u & 15) * 8;
        const float* src = W + (size_t)(gbase + g) * FDIM + c8;
        float4 v0 = *(const float4*)(src);
        float4 v1 = *(const float4*)(src + 4);
        float f[8] = {v0.x, v0.y, v0.z, v0.w, v1.x, v1.y, v1.z, v1.w};
        __nv_bfloat16 h[8], l[8];
        #pragma unroll
        for (int i = 0; i < 8; ++i) split_bf(f[i], h[i], l[i]);
        int du = g * ROW_U32 + (c8 >> 1);
        *(uint4*)&Bh[du] = make_uint4(pack2bf(h[0],h[1]), pack2bf(h[2],h[3]), pack2bf(h[4],h[5]), pack2bf(h[6],h[7]));
        *(uint4*)&Bl[du] = make_uint4(pack2bf(l[0],l[1]), pack2bf(l[2],l[3]), pack2bf(l[4],l[5]), pack2bf(l[6],l[7]));
    }
    // ---- fill A (rows, 128 x 128 k) hi/lo ----
    for (int u = tid; u < 128 * 16; u += 256) {
        int r = u >> 4, c8 = (u & 15) * 8;
        size_t srow;
        if (GATHER) srow = (size_t)idxs[r];
        else { int rr = r0 + r; if (rr >= nrows) rr = nrows - 1; srow = (size_t)rr; }
        const float* src = E + srow * FDIM + c8;
        float4 v0 = *(const float4*)(src);
        float4 v1 = *(const float4*)(src + 4);
        float f[8] = {v0.x, v0.y, v0.z, v0.w, v1.x, v1.y, v1.z, v1.w};
        __nv_bfloat16 h[8], l[8];
        #pragma unroll
        for (int i = 0; i < 8; ++i) split_bf(f[i], h[i], l[i]);
        int du = r * ROW_U32 + (c8 >> 1);
        *(uint4*)&Ah[du] = make_uint4(pack2bf(h[0],h[1]), pack2bf(h[2],h[3]), pack2bf(h[4],h[5]), pack2bf(h[6],h[7]));
        *(uint4*)&Al[du] = make_uint4(pack2bf(l[0],l[1]), pack2bf(l[2],l[3]), pack2bf(l[4],l[5]), pack2bf(l[6],l[7]));
    }
    __syncthreads();

    // ---- warp-tiled MMA: warp (wm, wn) owns rows wm*32..+31, gates wn*32..+31 ----
    const int wid  = tid >> 5, lane = tid & 31;
    const int wm   = wid & 3, wn = wid >> 2;
    const int g    = lane >> 2, t = lane & 3;

    float c[2][4][4];
    #pragma unroll
    for (int mi = 0; mi < 2; ++mi)
        #pragma unroll
        for (int ni = 0; ni < 4; ++ni)
            #pragma unroll
            for (int q = 0; q < 4; ++q) c[mi][ni][q] = 0.f;

    const uint32_t* Abase[3] = {Ah, Ah, Al};
    const uint32_t* Bbase[3] = {Bh, Bl, Bh};
    #pragma unroll
    for (int term = 0; term < 3; ++term) {
        const uint32_t* As = Abase[term];
        const uint32_t* Bs = Bbase[term];
        #pragma unroll
        for (int ks = 0; ks < 8; ++ks) {
            const int kc = ks * 8;
            uint32_t a[2][4];
            #pragma unroll
            for (int mi = 0; mi < 2; ++mi) {
                const uint32_t* ar = As + (wm * 32 + mi * 16 + g) * ROW_U32;
                a[mi][0] = ar[kc + t];
                a[mi][1] = ar[8 * ROW_U32 + kc + t];
                a[mi][2] = ar[kc + 4 + t];
                a[mi][3] = ar[8 * ROW_U32 + kc + 4 + t];
            }
            #pragma unroll
            for (int ni = 0; ni < 4; ++ni) {
                const uint32_t* br = Bs + (wn * 32 + ni * 8 + g) * ROW_U32;
                uint32_t b0 = br[kc + t];
                uint32_t b1 = br[kc + 4 + t];
                mma16816(c[0][ni], a[0][0], a[0][1], a[0][2], a[0][3], b0, b1);
                mma16816(c[1][ni], a[1][0], a[1][1], a[1][2], a[1][3], b0, b1);
            }
        }
    }

    // ---- bias + store ----
    float* outp = GATHER ? g_Gb : g_P;
    #pragma unroll
    for (int mi = 0; mi < 2; ++mi) {
        int row0 = r0 + wm * 32 + mi * 16 + g;
        #pragma unroll
        for (int ni = 0; ni < 4; ++ni) {
            int lc  = wn * 32 + ni * 8 + 2 * t;
            float bx = bias[lc], by = bias[lc + 1];
            if (row0 < nrows)
                *(float2*)&outp[(size_t)row0 * GDIM + gbase + lc] =
                    make_float2(c[mi][ni][0] + bx, c[mi][ni][1] + by);
            if (row0 + 8 < nrows)
                *(float2*)&outp[(size_t)(row0 + 8) * GDIM + gbase + lc] =
                    make_float2(c[mi][ni][2] + bx, c[mi][ni][3] + by);
        }
    }
}

// ============================================================================
// HMMA recurrence kernel: 32 nodes/block, 256 threads (8 warps).
// Per step k: g_P gather is software-pipelined across the MMA phase
// (first half issued before MMA, second half before the barrier; loads stay
// in flight across bar.sync). R = H@Whh^T via 3-term bf16-split HMMA staged
// to gs; cell phase adds gather + R, c in regs, h split hi/lo for next step.
// smem 112.9 KB -> 2 CTAs/SM.
// ============================================================================
#define LNB 32
#define BST 34                  // u32 row stride for Bh2/Bl2/Hh/Hl
#define GST 260                 // f32 row stride for gs
#define L_BH 0                              // 256*34 = 8704 u32
#define L_BL (L_BH + 256 * BST)
#define L_HH (L_BL + 256 * BST)
#define L_HL (L_HH + LNB * BST)
#define L_GS (L_HL + LNB * BST)
#define L_IX (L_GS + LNB * GST)
#define LSTM_SMEM ((L_IX + LNB * KNB) * 4)  // 112896 bytes

__global__ __launch_bounds__(256, 2) void lstm_kernel(
    const int* __restrict__ nidx, const float* __restrict__ Whh,
    float* __restrict__ out)
{
    extern __shared__ __align__(16) char smraw[];
    uint32_t* sm   = (uint32_t*)smraw;
    uint32_t* Bh2  = sm + L_BH;
    uint32_t* Bl2  = sm + L_BL;
    uint32_t* Hh   = sm + L_HH;
    uint32_t* Hl   = sm + L_HL;
    float*    gs   = (float*)(sm + L_GS);
    int*      idxs = (int*)(sm + L_IX);

    const int tid  = threadIdx.x;
    const int wid  = tid >> 5, lane = tid & 31;
    const int n0   = blockIdx.x * LNB;

    // ---- prologue: indices (grid-stride: 320 entries > 256 threads) ----
    for (int u = tid; u < LNB * KNB; u += 256) {
        int m = u / KNB, kk = u % KNB;
        int n = n0 + m; if (n >= N_NODES) n = N_NODES - 1;
        idxs[m * KNB + kk] = nidx[n * KNB + kk];
    }
    // ---- Whh hi/lo split into smem (thread = gate row) ----
    {
        const float* wr = Whh + tid * HDIM;
        uint32_t* bh = Bh2 + tid * BST;
        uint32_t* bl = Bl2 + tid * BST;
        #pragma unroll
        for (int i = 0; i < 16; ++i) {
            float4 v = *(const float4*)(wr + i * 4);
            __nv_bfloat16 h0,l0,h1,l1,h2,l2,h3,l3;
            split_bf(v.x,h0,l0); split_bf(v.y,h1,l1);
            split_bf(v.z,h2,l2); split_bf(v.w,h3,l3);
            *(uint2*)&bh[i*2] = make_uint2(pack2bf(h0,h1), pack2bf(h2,h3));
            *(uint2*)&bl[i*2] = make_uint2(pack2bf(l0,l1), pack2bf(l2,l3));
        }
    }
    __syncthreads();

    // cell-phase identity
    const int j    = tid & 63;
    const int msub = tid >> 6;
    float cst[8];
    #pragma unroll
    for (int q = 0; q < 8; ++q) cst[q] = 0.f;

    for (int k = 0; k < KNB; ++k) {
        // ---- prefetch gather, first half (in flight across the MMA phase) ----
        float xg[8][4];
        #pragma unroll
        for (int q = 0; q < 4; ++q) {
            int m = msub * 8 + q;
            const float* xp = g_P + (size_t)idxs[m * KNB + k] * GDIM + j;
            xg[q][0] = xp[0]; xg[q][1] = xp[64]; xg[q][2] = xp[128]; xg[q][3] = xp[192];
        }

        // ---- MMA phase: R = H @ Whh^T (3-term split), skip at k=0 ----
        if (k > 0) {
            const int wm = wid >> 2, wn = wid & 3;   // wm 0..1 (16 rows), wn 0..3 (64 gates)
            const int g = lane >> 2, t = lane & 3;

            uint32_t ah[4][4], al[4][4];
            const uint32_t* arh = Hh + (wm * 16 + g) * BST;
            const uint32_t* arl = Hl + (wm * 16 + g) * BST;
            #pragma unroll
            for (int ks = 0; ks < 4; ++ks) {
                const int kc = ks * 8;
                ah[ks][0] = arh[kc + t];           ah[ks][1] = arh[8 * BST + kc + t];
                ah[ks][2] = arh[kc + 4 + t];       ah[ks][3] = arh[8 * BST + kc + 4 + t];
                al[ks][0] = arl[kc + t];           al[ks][1] = arl[8 * BST + kc + t];
                al[ks][2] = arl[kc + 4 + t];       al[ks][3] = arl[8 * BST + kc + 4 + t];
            }
            float acc[8][4];
            #pragma unroll
            for (int ni = 0; ni < 8; ++ni)
                #pragma unroll
                for (int q = 0; q < 4; ++q) acc[ni][q] = 0.f;

            #pragma unroll
            for (int ni = 0; ni < 8; ++ni) {
                const uint32_t* brh = Bh2 + (wn * 64 + ni * 8 + g) * BST;
                const uint32_t* brl = Bl2 + (wn * 64 + ni * 8 + g) * BST;
                #pragma unroll
                for (int ks = 0; ks < 4; ++ks) {
                    const int kc = ks * 8;
                    uint32_t bh0 = brh[kc + t], bh1 = brh[kc + 4 + t];
                    uint32_t bl0 = brl[kc + t], bl1 = brl[kc + 4 + t];
                    mma16816(acc[ni], ah[ks][0], ah[ks][1], ah[ks][2], ah[ks][3], bh0, bh1);
                    mma16816(acc[ni], ah[ks][0], ah[ks][1], ah[ks][2], ah[ks][3], bl0, bl1);
                    mma16816(acc[ni], al[ks][0], al[ks][1], al[ks][2], al[ks][3], bh0, bh1);
                }
            }
            // stage R to gs
            const int r0 = wm * 16 + g;
            #pragma unroll
            for (int ni = 0; ni < 8; ++ni) {
                int col = wn * 64 + ni * 8 + 2 * t;
                *(float2*)&gs[r0 * GST + col]       = make_float2(acc[ni][0], acc[ni][1]);
                *(float2*)&gs[(r0 + 8) * GST + col] = make_float2(acc[ni][2], acc[ni][3]);
            }
        }

        // ---- prefetch gather, second half (in flight across the barrier) ----
        #pragma unroll
        for (int q = 4; q < 8; ++q) {
            int m = msub * 8 + q;
            const float* xp = g_P + (size_t)idxs[m * KNB + k] * GDIM + j;
            xg[q][0] = xp[0]; xg[q][1] = xp[64]; xg[q][2] = xp[128]; xg[q][3] = xp[192];
        }
        __syncthreads();

        // ---- cell phase: thread (j, msub) owns nodes m = msub*8+q ----
        #pragma unroll
        for (int q = 0; q < 8; ++q) {
            int m = msub * 8 + q;
            float gi = xg[q][0], gf = xg[q][1], gz = xg[q][2], go = xg[q][3];
            if (k > 0) {
                const float* gr = gs + m * GST + j;
                gi += gr[0]; gf += gr[64]; gz += gr[128]; go += gr[192];
            }
            float iv = sigm(gi), fv = sigm(gf), zv = tanhf(gz), ov = sigm(go);
            cst[q] = fv * cst[q] + iv * zv;
            float h = ov * tanhf(cst[q]);
            // split h for next step's MMA
            __nv_bfloat16 hh, hl;
            split_bf(h, hh, hl);
            *(__nv_bfloat16*)((char*)(Hh + m * BST) + j * 2) = hh;
            *(__nv_bfloat16*)((char*)(Hl + m * BST) + j * 2) = hl;
            if (k == KNB - 1 && n0 + m < N_NODES)
                out[(size_t)(n0 + m) * 128 + j] = h;
        }
        __syncthreads();
    }

    // ---- backward direction: single cell from zero state ----
    #pragma unroll
    for (int q = 0; q < 8; ++q) {
        int m = msub * 8 + q, n = n0 + m;
        if (n < N_NODES) {
            const float* gb = g_Gb + (size_t)n * GDIM + j;
            float cb = sigm(gb[0]) * tanhf(gb[128]);
            float hb = sigm(gb[192]) * tanhf(cb);
            out[(size_t)n * 128 + HDIM + j] = hb;
        }
    }
}

// ============================================================================
extern "C" void kernel_launch(void* const* d_in, const int* in_sizes, int n_in,
                              void* d_out, int out_size) {
    const int*   nidx  = (const int*)  d_in[0];
    const float* E     = (const float*)d_in[1];
    const float* Wih_f = (const float*)d_in[2];
    const float* Whh_f = (const float*)d_in[3];
    const float* bih_f = (const float*)d_in[4];
    const float* bhh_f = (const float*)d_in[5];
    const float* Wih_b = (const float*)d_in[6];
    const float* Whh_b = (const float*)d_in[7];  // unused: h0 = 0
    const float* bih_b = (const float*)d_in[8];
    const float* bhh_b = (const float*)d_in[9];
    float* out = (float*)d_out;
    (void)Whh_b; (void)in_sizes; (void)n_in; (void)out_size;

    cudaFuncSetAttribute(proj_tc<false>, cudaFuncAttributeMaxDynamicSharedMemorySize, TC_SMEM);
    cudaFuncSetAttribute(proj_tc<true>,  cudaFuncAttributeMaxDynamicSharedMemorySize, TC_SMEM);
    cudaFuncSetAttribute(lstm_kernel,    cudaFuncAttributeMaxDynamicSharedMemorySize, LSTM_SMEM);

    // 1) forward projected table: P = E @ Wih_f^T + (bih_f + bhh_f)   [HMMA bf16 x3]
    //    grid.x = gate quarter (fast) -> concurrent blocks share A via L2
    proj_tc<false><<<dim3(4, (VROWS + 127) / 128), 256, TC_SMEM>>>(
        E, Wih_f, bih_f, bhh_f, nullptr, VROWS);
    // 2) backward gates: Gb[n] = Wih_b @ E[idx[n][K-1]] + (bih_b + bhh_b)
    proj_tc<true><<<dim3(4, (N_NODES + 127) / 128), 256, TC_SMEM>>>(
        E, Wih_b, bih_b, bhh_b, nidx, N_NODES);
    // 3) forward recurrence (HMMA, pipelined gather) + both output halves
    lstm_kernel<<<(N_NODES + LNB - 1) / LNB, 256, LSTM_SMEM>>>(nidx, Whh_f, out);
}